// round 1
// baseline (speedup 1.0000x reference)
#include <cuda_runtime.h>
#include <cstdint>

#define POOL 7
#define NUM_ROIS 512
#define IMG_H 128
#define IMG_W 128
#define CH 1024

// One block per (roi, py, px). 256 threads x float4 = 1024 channels.
__global__ __launch_bounds__(256, 8)
void roi_pool_kernel(const float* __restrict__ img,
                     const int* __restrict__ rois,
                     float* __restrict__ out) {
    const int cell = blockIdx.x;          // roi*49 + py*7 + px
    const int roi  = cell / (POOL * POOL);
    const int rem  = cell - roi * (POOL * POOL);
    const int py   = rem / POOL;
    const int px   = rem - py * POOL;

    const int x = rois[roi * 4 + 0];
    const int y = rois[roi * 4 + 1];
    const int w = rois[roi * 4 + 2];
    const int h = rois[roi * 4 + 3];

    const float hf = (float)h;
    const float wf = (float)w;

    // half-pixel-center source coords, clamped (matches tf.image.resize bilinear)
    float ys = ((float)py + 0.5f) * hf * (1.0f / POOL) - 0.5f;
    float xs = ((float)px + 0.5f) * wf * (1.0f / POOL) - 0.5f;
    ys = fminf(fmaxf(ys, 0.0f), hf - 1.0f);
    xs = fminf(fmaxf(xs, 0.0f), wf - 1.0f);

    const int y0 = (int)floorf(ys);
    const int x0 = (int)floorf(xs);
    const int y1 = min(y0 + 1, h - 1);
    const int x1 = min(x0 + 1, w - 1);
    const float fy = ys - (float)y0;
    const float fx = xs - (float)x0;

    // absolute pixel indices
    const int ay0 = y + y0, ay1 = y + y1;
    const int ax0 = x + x0, ax1 = x + x1;

    const float4* p00 = (const float4*)(img + ((size_t)(ay0 * IMG_W + ax0)) * CH);
    const float4* p01 = (const float4*)(img + ((size_t)(ay0 * IMG_W + ax1)) * CH);
    const float4* p10 = (const float4*)(img + ((size_t)(ay1 * IMG_W + ax0)) * CH);
    const float4* p11 = (const float4*)(img + ((size_t)(ay1 * IMG_W + ax1)) * CH);

    float4* o = (float4*)(out + (size_t)cell * CH);

    const int t = threadIdx.x;            // 0..255 -> float4 lane

    const float w00 = (1.0f - fy) * (1.0f - fx);
    const float w01 = (1.0f - fy) * fx;
    const float w10 = fy * (1.0f - fx);
    const float w11 = fy * fx;

    float4 a = __ldg(p00 + t);
    float4 b = __ldg(p01 + t);
    float4 c = __ldg(p10 + t);
    float4 d = __ldg(p11 + t);

    float4 r;
    r.x = a.x * w00 + b.x * w01 + c.x * w10 + d.x * w11;
    r.y = a.y * w00 + b.y * w01 + c.y * w10 + d.y * w11;
    r.z = a.z * w00 + b.z * w01 + c.z * w10 + d.z * w11;
    r.w = a.w * w00 + b.w * w01 + c.w * w10 + d.w * w11;

    o[t] = r;
}

extern "C" void kernel_launch(void* const* d_in, const int* in_sizes, int n_in,
                              void* d_out, int out_size) {
    const float* img  = (const float*)d_in[0];
    const int*   rois = (const int*)d_in[1];
    float*       out  = (float*)d_out;

    const int n_cells = NUM_ROIS * POOL * POOL;   // 25088
    roi_pool_kernel<<<n_cells, 256>>>(img, rois, out);
}